// round 15
// baseline (speedup 1.0000x reference)
#include <cuda_runtime.h>
#include <math.h>

#define NIMG   2048          // B*C
#define PI_F   3.14159265358979323846f

typedef unsigned long long ull;

// Scratch (device globals; allocation-free per harness rules)
__device__ __align__(16) float2 g_buf0[NIMG * 16384];
__device__ __align__(16) float2 g_buf1[NIMG * 16384];
__device__ float g_mag[8 * 49];
__device__ float g_kern[8 * 49];

// ---------------------------------------------------------------------------
// packed f32x2 helpers
// ---------------------------------------------------------------------------
__device__ __forceinline__ ull pk2(float lo, float hi) {
    ull r; asm("mov.b64 %0,{%1,%2};" : "=l"(r) : "f"(lo), "f"(hi)); return r;
}
__device__ __forceinline__ void upk2(ull v, float& lo, float& hi) {
    asm("mov.b64 {%0,%1}, %2;" : "=f"(lo), "=f"(hi) : "l"(v));
}
__device__ __forceinline__ ull fma2(ull a, ull b, ull c) {
    ull d; asm("fma.rn.f32x2 %0, %1, %2, %3;" : "=l"(d) : "l"(a), "l"(b), "l"(c));
    return d;
}

// ---------------------------------------------------------------------------
// Register/shuffle 128-point FFT (four-step: radix-4 regs + 32-pt lane FFT)
// Input : x[a] = element (lane + 32a)
// Output: x[c] = X[4*lane + c]
// ---------------------------------------------------------------------------
struct cpx { float r, i; };
__device__ __forceinline__ cpx cadd(cpx a, cpx b){ return {a.r+b.r, a.i+b.i}; }
__device__ __forceinline__ cpx csub(cpx a, cpx b){ return {a.r-b.r, a.i-b.i}; }
__device__ __forceinline__ cpx cmul(cpx a, cpx b){
    return {a.r*b.r - a.i*b.i, a.r*b.i + a.i*b.r};
}

struct Twid {
    cpx w1, w2, w3;        // W128^{l}, ^2l, ^3l
    cpx t16, t8, t4, t2;   // 32-FFT stage twiddles
    int brl;               // bitrev5(lane)
};

template<bool INV>
__device__ __forceinline__ Twid make_twid(int lane) {
    Twid T;
    const float sgn = INV ? 1.f : -1.f;
    float a1 = sgn * (2.f * PI_F / 128.f) * (float)lane;
    __sincosf(a1, &T.w1.i, &T.w1.r);
    T.w2 = cmul(T.w1, T.w1);
    T.w3 = cmul(T.w2, T.w1);
    float ah;
    ah = sgn * PI_F * (float)(lane & 15) / 16.f; __sincosf(ah, &T.t16.i, &T.t16.r);
    ah = sgn * PI_F * (float)(lane & 7)  / 8.f;  __sincosf(ah, &T.t8.i,  &T.t8.r);
    ah = sgn * PI_F * (float)(lane & 3)  / 4.f;  __sincosf(ah, &T.t4.i,  &T.t4.r);
    ah = sgn * PI_F * (float)(lane & 1)  / 2.f;  __sincosf(ah, &T.t2.i,  &T.t2.r);
    T.brl = (int)(__brev((unsigned)lane) >> 27);
    return T;
}

__device__ __forceinline__ cpx shflx(cpx v, int h) {
    cpx o;
    o.r = __shfl_xor_sync(0xffffffffu, v.r, h);
    o.i = __shfl_xor_sync(0xffffffffu, v.i, h);
    return o;
}

__device__ __forceinline__ void bf(cpx& v, int lane, int h, cpx tw, bool usetw) {
    cpx o = shflx(v, h);
    if (lane & h) {
        cpx d = csub(o, v);
        v = usetw ? cmul(d, tw) : d;
    } else {
        v = cadd(v, o);
    }
}

template<bool INV>
__device__ __forceinline__ void fft128(cpx x[4], const Twid& T, int lane) {
    cpx s0 = cadd(x[0], x[2]), d0 = csub(x[0], x[2]);
    cpx s1 = cadd(x[1], x[3]), d1 = csub(x[1], x[3]);
    cpx jd1 = { -d1.i, d1.r };
    cpx F0 = cadd(s0, s1);
    cpx F2 = csub(s0, s1);
    cpx F1, F3;
    if (INV) { F1 = cadd(d0, jd1); F3 = csub(d0, jd1); }
    else     { F1 = csub(d0, jd1); F3 = cadd(d0, jd1); }
    x[0] = F0;
    x[1] = cmul(F1, T.w1);
    x[2] = cmul(F2, T.w2);
    x[3] = cmul(F3, T.w3);
#pragma unroll
    for (int c = 0; c < 4; ++c) {
        bf(x[c], lane, 16, T.t16, true);
        bf(x[c], lane, 8,  T.t8,  true);
        bf(x[c], lane, 4,  T.t4,  true);
        bf(x[c], lane, 2,  T.t2,  true);
        bf(x[c], lane, 1,  T.t2,  false);
        float rr = __shfl_sync(0xffffffffu, x[c].r, T.brl);
        float ii = __shfl_sync(0xffffffffu, x[c].i, T.brl);
        x[c].r = rr; x[c].i = ii;
    }
}

// swizzled smem index for a [row][col] 128x128 float2 buffer
__device__ __forceinline__ int swz(int row, int col) {
    return row * 128 + (col ^ ((row >> 2) & 31));
}

// ---------------------------------------------------------------------------
// FWD2D: full forward FFT2 (ortho, 1/128) with fftshift on both axes.
// in : x_low[img][y][x]        out: S[img][fxs][fys]
// One CTA per image, 512 threads, 128 KB dynamic smem.
// ---------------------------------------------------------------------------
__global__ void __launch_bounds__(512)
fwd2d_kernel(const float* __restrict__ in, float2* __restrict__ S)
{
    extern __shared__ float2 buf[];   // 16384 float2, swizzled [row][col]
    const int tid = threadIdx.x, warp = tid >> 5, lane = tid & 31;
    const int img = blockIdx.x;
    const size_t ibase = (size_t)img * 16384;
    Twid T = make_twid<false>(lane);

    // Phase 1: row FFTs over x (gmem -> regs -> transposed smem)
#pragma unroll
    for (int q = 0; q < 8; ++q) {
        int y = warp * 8 + q;
        const float* p = in + ibase + (size_t)y * 128;
        cpx x[4];
#pragma unroll
        for (int a = 0; a < 4; ++a) x[a] = { p[lane + 32 * a] * (1.f / 128.f), 0.f };
        fft128<false>(x, T, lane);
        int mh = lane ^ 16;                 // fftshift over fx
#pragma unroll
        for (int c = 0; c < 4; ++c) {
            int fxs = 4 * mh + c;
            buf[swz(fxs, y)] = make_float2(x[c].r, x[c].i);
        }
    }
    __syncthreads();

    // Phase 2: column FFTs over y (smem rows -> gmem, fftshift on store)
#pragma unroll
    for (int q = 0; q < 8; ++q) {
        int fxs = warp * 8 + q;
        cpx x[4];
#pragma unroll
        for (int a = 0; a < 4; ++a) {
            float2 v = buf[swz(fxs, lane + 32 * a)];
            x[a] = { v.x, v.y };
        }
        fft128<false>(x, T, lane);
        float2* o = S + ibase + (size_t)fxs * 128;
        int mh = lane ^ 16;                 // fftshift over fy
        float4 v0 = make_float4(x[0].r, x[0].i, x[1].r, x[1].i);
        float4 v1 = make_float4(x[2].r, x[2].i, x[3].r, x[3].i);
        *(float4*)(o + 4 * mh)     = v0;
        *(float4*)(o + 4 * mh + 2) = v1;
    }
}

// ---------------------------------------------------------------------------
// mag: mean over 256 channels of |S| at center 7x7. Block = (b, i).
// ---------------------------------------------------------------------------
__global__ void __launch_bounds__(256)
mag_kernel(const float2* __restrict__ S, float* __restrict__ mag)
{
    __shared__ float red[256];
    const int bi = blockIdx.x;
    const int b = bi / 49, i = bi % 49;
    const int dy = i / 7, dx = i % 7;
    const int c = threadIdx.x;
    float2 v = S[(size_t)(b * 256 + c) * 16384 + (size_t)(61 + dx) * 128 + (61 + dy)];
    red[c] = sqrtf(v.x * v.x + v.y * v.y);
    __syncthreads();
    for (int s = 128; s > 0; s >>= 1) {
        if (c < s) red[c] += red[c + s];
        __syncthreads();
    }
    if (c == 0) mag[b * 49 + i] = red[0] * (1.f / 256.f);
}

// ---------------------------------------------------------------------------
// MLP (49->32->3) + anisotropic kernel generation. One warp per batch.
// ---------------------------------------------------------------------------
__global__ void __launch_bounds__(256)
mlp_kernel(const float* __restrict__ w1, const float* __restrict__ b1,
           const float* __restrict__ w2, const float* __restrict__ b2,
           const float* __restrict__ mag, float* __restrict__ kern)
{
    const int tid = threadIdx.x;
    const int b = tid >> 5;
    const int lane = tid & 31;
    __shared__ float sh_h[8][32];
    __shared__ float sp[8][3];

    float h = b1[lane];
    for (int i = 0; i < 49; ++i) h += mag[b * 49 + i] * w1[lane * 49 + i];
    h = fmaxf(h, 0.f);
    sh_h[b][lane] = h;
    __syncthreads();

    if (lane < 3) {
        float p = b2[lane];
        for (int j = 0; j < 32; ++j) p += sh_h[b][j] * w2[lane * 32 + j];
        sp[b][lane] = p;
    }
    __syncthreads();

    float p0 = sp[b][0], p1 = sp[b][1], p2 = sp[b][2];
    float theta = atan2f(p0, p1) * 0.5f + PI_F * 0.5f;
    float lam1  = expf(p2);
    float lam2  = 1.f / (lam1 + 1e-8f);
    float ct = cosf(theta), st = sinf(theta);
    float inv1 = 1.f / (2.f * lam1 * lam1);
    float inv2 = 1.f / (2.f * lam2 * lam2);

    float v0 = 0.f, v1 = 0.f;
    {
        int idx = lane;
        float yy = (float)(idx / 7) - 3.f;
        float xx = (float)(idx % 7) - 3.f;
        float xr =  xx * ct + yy * st;
        float yr = -xx * st + yy * ct;
        v0 = expf(-(xr * xr * inv1 + yr * yr * inv2));
    }
    {
        int idx = lane + 32;
        if (idx < 49) {
            float yy = (float)(idx / 7) - 3.f;
            float xx = (float)(idx % 7) - 3.f;
            float xr =  xx * ct + yy * st;
            float yr = -xx * st + yy * ct;
            v1 = expf(-(xr * xr * inv1 + yr * yr * inv2));
        }
    }
    float s = v0 + v1;
    for (int off = 16; off; off >>= 1) s += __shfl_xor_sync(0xffffffffu, s, off);
    float inv_sum = 1.f / (s + 1e-8f);
    kern[b * 49 + lane] = v0 * inv_sum;
    if (lane + 32 < 49) kern[b * 49 + lane + 32] = v1 * inv_sum;
}

// ---------------------------------------------------------------------------
// INV2D: depthwise 7x7 conv (zero pad, in smem) + inverse FFT2 (ortho 1/128,
// ifftshift on load of both axes). One CTA per image, 512 threads, 128 KB smem.
// in : S[img][xs][ys]      out: Z[img][y][x]  (float)
// conv weight for (xs offset rz, ys offset s) = kern[s*7+rz]
// ---------------------------------------------------------------------------
__global__ void __launch_bounds__(512)
inv2d_kernel(const float2* __restrict__ S, const float* __restrict__ kern,
             float* __restrict__ Z)
{
    extern __shared__ float2 buf[];   // 16384 float2, swizzled
    __shared__ ull kk2[49];
    const int tid = threadIdx.x, warp = tid >> 5, lane = tid & 31;
    const int img = blockIdx.x;
    const int b = img >> 8;
    const size_t ibase = (size_t)img * 16384;

    if (tid < 49) { float w = kern[b * 49 + tid]; kk2[tid] = pk2(w, w); }

    // Phase 0: load S into swizzled smem
    {
        const float2* src = S + ibase;
#pragma unroll
        for (int t = 0; t < 32; ++t) {
            int i = t * 512 + tid;
            int xs = i >> 7, ys = i & 127;
            buf[swz(xs, ys)] = src[i];
        }
    }
    __syncthreads();

    // Phase 1: conv into registers. thread: ys = tid&127, xs-group g = tid>>7
    ull acc[32];
    {
        const int ty = tid & 127;
        const int g  = tid >> 7;
        const int x0 = g * 32;
#pragma unroll
        for (int i = 0; i < 32; ++i) acc[i] = pk2(0.f, 0.f);
#pragma unroll
        for (int z = 0; z < 38; ++z) {
            int gx = x0 - 3 + z;
            if ((unsigned)gx >= 128u) continue;
            int sw = (gx >> 2) & 31;
            const float2* row = buf + gx * 128;
            ull v[7];
#pragma unroll
            for (int s = 0; s < 7; ++s) {
                int gy = ty - 3 + s;
                float2 t = ((unsigned)gy < 128u) ? row[gy ^ sw] : make_float2(0.f, 0.f);
                v[s] = pk2(t.x, t.y);
            }
#pragma unroll
            for (int i = 0; i < 32; ++i) {
                int rz = z - i;
                if (rz < 0 || rz > 6) continue;
#pragma unroll
                for (int s = 0; s < 7; ++s)
                    acc[i] = fma2(v[s], kk2[s * 7 + rz], acc[i]);
            }
        }
    }
    __syncthreads();
    // write conv results back in place
    {
        const int ty = tid & 127;
        const int g  = tid >> 7;
#pragma unroll
        for (int i = 0; i < 32; ++i) {
            int xs = g * 32 + i;
            float lo, hi; upk2(acc[i], lo, hi);
            buf[swz(xs, ty)] = make_float2(lo, hi);
        }
    }
    __syncthreads();

    // Phase 2: inverse FFT over ys (ifftshift on load, 1/128), transpose in place
    Twid T = make_twid<true>(lane);
    cpx res[8][4];
#pragma unroll
    for (int q = 0; q < 8; ++q) {
        int r = warp * 8 + q;
        cpx x[4];
#pragma unroll
        for (int a = 0; a < 4; ++a) {
            float2 v = buf[swz(r, (lane + 32 * a) ^ 64)];
            x[a] = { v.x * (1.f / 128.f), v.y * (1.f / 128.f) };
        }
        fft128<true>(x, T, lane);
#pragma unroll
        for (int c = 0; c < 4; ++c) res[q][c] = x[c];
    }
    __syncthreads();
#pragma unroll
    for (int q = 0; q < 8; ++q) {
        int r = warp * 8 + q;
#pragma unroll
        for (int c = 0; c < 4; ++c) {
            int y = 4 * lane + c;
            buf[swz(y, r)] = make_float2(res[q][c].r, res[q][c].i);
        }
    }
    __syncthreads();

    // Phase 3: inverse FFT over xs (ifftshift on load), real out, direct store
#pragma unroll
    for (int q = 0; q < 8; ++q) {
        int y = warp * 8 + q;
        cpx x[4];
#pragma unroll
        for (int a = 0; a < 4; ++a) {
            float2 v = buf[swz(y, (lane + 32 * a) ^ 64)];
            x[a] = { v.x, v.y };
        }
        fft128<true>(x, T, lane);
        float4 v = make_float4(x[0].r, x[1].r, x[2].r, x[3].r);
        *(float4*)(Z + ibase + (size_t)y * 128 + 4 * lane) = v;
    }
}

// ---------------------------------------------------------------------------
// out[b,o,y,x] = sum_c refine[o,c] * Z[b,c,y,x] + bilinear_up(x_high)
// fp32 tiled GEMM with packed fma.rn.f32x2
// ---------------------------------------------------------------------------
__global__ void __launch_bounds__(256)
gemm_kernel(const float* __restrict__ refine, const float* __restrict__ Z,
            const float* __restrict__ xh, float* __restrict__ out)
{
    __shared__ float As[16][132];
    __shared__ __align__(16) float Bs[16][132];

    const int b    = blockIdx.z;
    const int ot   = blockIdx.y;
    const int yrow = blockIdx.x;
    const int tid  = threadIdx.x;
    const int txq  = tid & 15;
    const int tyq  = tid >> 4;

    const float* Zb = Z + (size_t)b * 256 * 16384 + (size_t)yrow * 128;

    ull acc2[8][4];
#pragma unroll
    for (int i = 0; i < 8; ++i)
#pragma unroll
        for (int j = 0; j < 4; ++j) acc2[i][j] = pk2(0.f, 0.f);

    for (int k0 = 0; k0 < 256; k0 += 16) {
#pragma unroll
        for (int i = 0; i < 8; ++i) {
            int o = (tid >> 4) + i * 16;
            int k = tid & 15;
            As[k][o] = refine[(size_t)(ot * 128 + o) * 256 + k0 + k];
        }
#pragma unroll
        for (int i = 0; i < 2; ++i) {
            int k  = (tid >> 5) + i * 8;
            int x4 = (tid & 31) * 4;
            float4 v = *(const float4*)(Zb + (size_t)(k0 + k) * 16384 + x4);
            *(float4*)&Bs[k][x4] = v;
        }
        __syncthreads();
#pragma unroll
        for (int k = 0; k < 16; ++k) {
            ull a2[8], b2[4];
#pragma unroll
            for (int i = 0; i < 8; ++i) {
                float av = As[k][tyq * 8 + i];
                a2[i] = pk2(av, av);
            }
#pragma unroll
            for (int j = 0; j < 4; ++j) {
                float2 bv = *(const float2*)&Bs[k][txq * 8 + 2 * j];
                b2[j] = pk2(bv.x, bv.y);
            }
#pragma unroll
            for (int i = 0; i < 8; ++i)
#pragma unroll
                for (int j = 0; j < 4; ++j)
                    acc2[i][j] = fma2(a2[i], b2[j], acc2[i][j]);
        }
        __syncthreads();
    }

    const int y = yrow;
    int ym0, ym1; float wy0, wy1;
    if ((y & 1) == 0) { int u = y >> 1; ym0 = (u > 0) ? u - 1 : 0; ym1 = u; wy0 = 0.25f; wy1 = 0.75f; }
    else              { int u = y >> 1; ym0 = u; ym1 = (u < 63) ? u + 1 : 63; wy0 = 0.75f; wy1 = 0.25f; }

#pragma unroll
    for (int i = 0; i < 8; ++i) {
        int o = ot * 128 + tyq * 8 + i;
        const float* xr0 = xh + ((size_t)(b * 256 + o) * 64 + ym0) * 64;
        const float* xr1 = xh + ((size_t)(b * 256 + o) * 64 + ym1) * 64;
        float* po = out + (size_t)(b * 256 + o) * 16384 + (size_t)y * 128;
        float accr[8];
#pragma unroll
        for (int j = 0; j < 4; ++j) upk2(acc2[i][j], accr[2 * j], accr[2 * j + 1]);
#pragma unroll
        for (int j = 0; j < 8; ++j) {
            int x = txq * 8 + j;
            int xm0, xm1; float wx0, wx1;
            if ((x & 1) == 0) { int u = x >> 1; xm0 = (u > 0) ? u - 1 : 0; xm1 = u; wx0 = 0.25f; wx1 = 0.75f; }
            else              { int u = x >> 1; xm0 = u; xm1 = (u < 63) ? u + 1 : 63; wx0 = 0.75f; wx1 = 0.25f; }
            float up = wy0 * (wx0 * xr0[xm0] + wx1 * xr0[xm1])
                     + wy1 * (wx0 * xr1[xm0] + wx1 * xr1[xm1]);
            po[x] = accr[j] + up;
        }
    }
}

// ---------------------------------------------------------------------------
// Launch
// ---------------------------------------------------------------------------
extern "C" void kernel_launch(void* const* d_in, const int* in_sizes, int n_in,
                              void* d_out, int out_size)
{
    const float* x_high = (const float*)d_in[0];
    const float* x_low  = (const float*)d_in[1];
    const float* w1     = (const float*)d_in[2];
    const float* b1     = (const float*)d_in[3];
    const float* w2     = (const float*)d_in[4];
    const float* b2     = (const float*)d_in[5];
    const float* refine = (const float*)d_in[6];
    float* out = (float*)d_out;

    float2 *buf0, *buf1;
    float *magp, *kernp;
    cudaGetSymbolAddress((void**)&buf0,  g_buf0);
    cudaGetSymbolAddress((void**)&buf1,  g_buf1);
    cudaGetSymbolAddress((void**)&magp,  g_mag);
    cudaGetSymbolAddress((void**)&kernp, g_kern);

    const int SMEM = 16384 * sizeof(float2);   // 128 KB
    cudaFuncSetAttribute(fwd2d_kernel, cudaFuncAttributeMaxDynamicSharedMemorySize, SMEM);
    cudaFuncSetAttribute(inv2d_kernel, cudaFuncAttributeMaxDynamicSharedMemorySize, SMEM);

    // 1) full forward FFT2 (ortho) + fftshift -> S[img][fxs][fys]
    fwd2d_kernel<<<NIMG, 512, SMEM>>>(x_low, buf1);

    // 2) center 7x7 magnitude means
    mag_kernel<<<8 * 49, 256>>>(buf1, magp);

    // 3) MLP + anisotropic kernel
    mlp_kernel<<<1, 256>>>(w1, b1, w2, b2, magp, kernp);

    // 4) conv + inverse FFT2 (ifftshift + ortho) -> Z[img][y][x]
    inv2d_kernel<<<NIMG, 512, SMEM>>>(buf1, kernp, (float*)buf0);

    // 5) channel mix + fused bilinear upsample add
    gemm_kernel<<<dim3(128, 2, 8), 256>>>(refine, (const float*)buf0, x_high, out);
}